// round 4
// baseline (speedup 1.0000x reference)
#include <cuda_runtime.h>
#include <cuda_bf16.h>
#include <cstdint>
#include <cstddef>

// ---------------- problem constants ----------------
#define NB_B   64
#define MAXT   511
#define TP1    512
#define S_DIM  1024
#define H_DIM  4096

// ---------------- tiling ----------------
#define BM 128
#define BN 256            // H columns per chunk
#define BK 64             // K per pipeline stage
#define N_CHUNKS  (H_DIM / BN)     // 16
#define K_STAGES  (S_DIM / BK)     // 16
#define TOT_GS    (N_CHUNKS * K_STAGES)  // 256

#define ROW_B  144        // 64 bf16 = 128B data + 16B pad (conflict-free ldmatrix)

// ---------------- SMEM layout (byte offsets into dynamic smem) ----------------
#define SM_W2   0                         // 4096 float4  = 65536
#define SM_B1   65536                     // 4096 float   = 16384
#define SM_LG   81920                     // scratch      = 4096
#define SM_A    86016                     // 2 x 128*144  = 36864
#define A_STAGE 18432
#define SM_B    122880                    // 2 x 256*144  = 73728
#define B_STAGE 36864
#define SMEM_BYTES 196608

// ---------------- scratch (device globals; zero-initialized at load) ----------
__device__ __align__(1024) __nv_bfloat16 g_s[(size_t)NB_B * TP1 * S_DIM];   // bf16 s; rows t>=len stay 0
__device__ __align__(1024) __nv_bfloat16 g_w1t[(size_t)H_DIM * S_DIM];      // W1^T bf16 (N-major rows, K contig)

// ---------------- PTX helpers (all baseline <= sm_90 features) ----------------
__device__ __forceinline__ uint32_t smem_u32(const void* p) {
    uint32_t a;
    asm("{ .reg .u64 t; cvta.to.shared.u64 t, %1; cvt.u32.u64 %0, t; }" : "=r"(a) : "l"(p));
    return a;
}

__device__ __forceinline__ void cp_async16(uint32_t dst, const void* src) {
    asm volatile("cp.async.cg.shared.global [%0], [%1], 16;" :: "r"(dst), "l"(src) : "memory");
}
#define CP_COMMIT()  asm volatile("cp.async.commit_group;" ::: "memory")
#define CP_WAIT1()   asm volatile("cp.async.wait_group 1;" ::: "memory")

__device__ __forceinline__ void ldsm4(uint32_t* r, uint32_t addr) {
    asm volatile("ldmatrix.sync.aligned.m8n8.x4.shared.b16 {%0,%1,%2,%3}, [%4];"
                 : "=r"(r[0]), "=r"(r[1]), "=r"(r[2]), "=r"(r[3]) : "r"(addr));
}

__device__ __forceinline__ void mma16816(float* d, const uint32_t* a, const uint32_t* b) {
    asm volatile(
        "mma.sync.aligned.m16n8k16.row.col.f32.bf16.bf16.f32 "
        "{%0,%1,%2,%3}, {%4,%5,%6,%7}, {%8,%9}, {%0,%1,%2,%3};"
        : "+f"(d[0]), "+f"(d[1]), "+f"(d[2]), "+f"(d[3])
        : "r"(a[0]), "r"(a[1]), "r"(a[2]), "r"(a[3]), "r"(b[0]), "r"(b[1]));
}

// ---------------- preprocessing: s fp32 -> bf16 (only t < len rows) ----------------
__global__ void conv_s_kernel(const float* __restrict__ s,
                              const int* __restrict__ lengths,
                              float* __restrict__ out) {
    int row = blockIdx.x;             // b*512 + t
    if (row == 0 && threadIdx.x == 0) out[0] = 0.0f;   // un-poison the output
    int b = row >> 9;
    int t = row & 511;
    int len = lengths[b];
    if (t >= len) return;             // rows >= len remain zero

    const float4* src = (const float4*)(s + (size_t)row * S_DIM);
    __nv_bfloat162* dst = (__nv_bfloat162*)(g_s + (size_t)row * S_DIM);
    for (int i = threadIdx.x; i < S_DIM / 4; i += blockDim.x) {
        float4 v = src[i];
        dst[i * 2 + 0] = __floats2bfloat162_rn(v.x, v.y);
        dst[i * 2 + 1] = __floats2bfloat162_rn(v.z, v.w);
    }
}

// ---------------- preprocessing: W1 (S,H) fp32 -> W1^T (H,S) bf16 ----------------
__global__ void conv_w1t_kernel(const float* __restrict__ W1) {
    __shared__ float tile[32][33];
    int n0 = blockIdx.x * 32;
    int k0 = blockIdx.y * 32;
    for (int r = threadIdx.y; r < 32; r += 8)
        tile[r][threadIdx.x] = W1[(size_t)(k0 + r) * H_DIM + n0 + threadIdx.x];
    __syncthreads();
    for (int r = threadIdx.y; r < 32; r += 8)
        g_w1t[(size_t)(n0 + r) * S_DIM + k0 + threadIdx.x] =
            __float2bfloat16(tile[threadIdx.x][r]);
}

// ---------------- main fused kernel ----------------
__global__ void __launch_bounds__(256, 1)
traj_main_kernel(const int* __restrict__ actions,
                 const int* __restrict__ lengths,
                 const float* __restrict__ b1,
                 const float* __restrict__ W2,
                 const float* __restrict__ b2,
                 float* __restrict__ out) {
    int b = blockIdx.y;
    int m0 = blockIdx.x * BM;
    int len = lengths[b];
    if (len > MAXT) len = MAXT;
    if (m0 >= len) return;            // whole tile masked out

    extern __shared__ char smem[];
    uint32_t sb = smem_u32(smem);
    float4* w2s = (float4*)(smem + SM_W2);
    float*  b1s = (float*)(smem + SM_B1);
    float*  lg  = (float*)(smem + SM_LG);

    int tid = threadIdx.x;
    int wid = tid >> 5;
    int lane = tid & 31;
    int wm = wid & 3;                 // M strip (32 rows)
    int wn = wid >> 2;                // N half (128 cols)

    // preload W2[:,0:4] and b1 to smem (visible after first __syncthreads)
    for (int i = tid; i < H_DIM; i += 256) {
        w2s[i] = *(const float4*)(W2 + (size_t)i * 32);
        b1s[i] = b1[i];
    }

    const __nv_bfloat16* Abase = g_s + ((size_t)(b * TP1 + m0)) * S_DIM;
    uint32_t smA = sb + SM_A;
    uint32_t smB = sb + SM_B;

    // per-lane ldmatrix address components
    int aRow = wm * 32 + (lane & 15);              // + mt*16
    int aKof = (lane >> 4) * 8;                    // elements
    int bRow = wn * 128 + ((lane & 16) ? 8 : 0) + (lane & 7);   // + p*16
    int bKof = ((lane >> 3) & 1) * 8;

    auto issue = [&](int gs) {
        int nc = gs >> 4, s = gs & 15;
        int k0 = s * BK;
        const __nv_bfloat16* ag = Abase + k0;
        const __nv_bfloat16* bg = g_w1t + (size_t)(nc * BN) * S_DIM + k0;
        uint32_t Ab = smA + (gs & 1) * A_STAGE;
        uint32_t Bb = smB + (gs & 1) * B_STAGE;
#pragma unroll
        for (int t = 0; t < 4; t++) {              // A: 128 rows x 8 chunks
            int idx = tid + t * 256;
            int row = idx >> 3, ch = idx & 7;
            cp_async16(Ab + row * ROW_B + ch * 16, ag + (size_t)row * S_DIM + ch * 8);
        }
#pragma unroll
        for (int t = 0; t < 8; t++) {              // B: 256 rows x 8 chunks
            int idx = tid + t * 256;
            int row = idx >> 3, ch = idx & 7;
            cp_async16(Bb + row * ROW_B + ch * 16, bg + (size_t)row * S_DIM + ch * 8);
        }
        CP_COMMIT();
    };

    float c[2][16][4];
#pragma unroll
    for (int mt = 0; mt < 2; mt++)
#pragma unroll
        for (int nt = 0; nt < 16; nt++)
#pragma unroll
            for (int k = 0; k < 4; k++) c[mt][nt][k] = 0.f;

    float acc[2][2][4] = {};          // [mt][rowhalf][logit]

    issue(0);
    issue(1);

#pragma unroll 1
    for (int gs = 0; gs < TOT_GS; gs++) {
        CP_WAIT1();
        __syncthreads();

        uint32_t Ab = smA + (gs & 1) * A_STAGE;
        uint32_t Bb = smB + (gs & 1) * B_STAGE;
#pragma unroll
        for (int kk = 0; kk < 4; kk++) {           // 4 x k16 per stage
            uint32_t a0[4], a1[4];
            ldsm4(a0, Ab + (uint32_t)(aRow * ROW_B)        + (uint32_t)(kk * 16 + aKof) * 2);
            ldsm4(a1, Ab + (uint32_t)((aRow + 16) * ROW_B) + (uint32_t)(kk * 16 + aKof) * 2);
#pragma unroll
            for (int p = 0; p < 8; p++) {          // n-tile pairs
                uint32_t bf[4];
                ldsm4(bf, Bb + (uint32_t)((bRow + p * 16) * ROW_B) + (uint32_t)(kk * 16 + bKof) * 2);
                mma16816(c[0][2 * p],     a0, bf);
                mma16816(c[0][2 * p + 1], a0, bf + 2);
                mma16816(c[1][2 * p],     a1, bf);
                mma16816(c[1][2 * p + 1], a1, bf + 2);
            }
        }
        __syncthreads();              // everyone done reading this buffer

        if (gs + 2 < TOT_GS) issue(gs + 2);
        else                 CP_COMMIT();          // keep group cadence

        if ((gs & 15) == 15) {
            // ---- fused epilogue for N-chunk nc (overlaps in-flight cp.async) ----
            int nbch = (gs >> 4) * BN + wn * 128;
#pragma unroll
            for (int mt = 0; mt < 2; mt++)
#pragma unroll
                for (int nt = 0; nt < 16; nt++) {
                    int n0 = nbch + nt * 8 + (lane & 3) * 2;
#pragma unroll
                    for (int j = 0; j < 2; j++) {
                        int n = n0 + j;
                        float bb = b1s[n];
                        float4 w = w2s[n];
                        float h0 = fmaxf(c[mt][nt][j] + bb, 0.f);
                        float h1 = fmaxf(c[mt][nt][2 + j] + bb, 0.f);
                        acc[mt][0][0] += h0 * w.x; acc[mt][0][1] += h0 * w.y;
                        acc[mt][0][2] += h0 * w.z; acc[mt][0][3] += h0 * w.w;
                        acc[mt][1][0] += h1 * w.x; acc[mt][1][1] += h1 * w.y;
                        acc[mt][1][2] += h1 * w.z; acc[mt][1][3] += h1 * w.w;
                        c[mt][nt][j] = 0.f; c[mt][nt][2 + j] = 0.f;   // reset for next chunk
                    }
                }
        }
    }

    // ---- reduce 4-logit partials: quad shuffle, then combine the 2 N-halves ----
#pragma unroll
    for (int mt = 0; mt < 2; mt++)
#pragma unroll
        for (int h = 0; h < 2; h++)
#pragma unroll
            for (int k = 0; k < 4; k++) {
                float v = acc[mt][h][k];
                v += __shfl_xor_sync(0xffffffffu, v, 1);
                v += __shfl_xor_sync(0xffffffffu, v, 2);
                acc[mt][h][k] = v;
            }
    int q = lane >> 2;
    if (wn == 0 && (lane & 3) == 0) {
#pragma unroll
        for (int mt = 0; mt < 2; mt++)
#pragma unroll
            for (int h = 0; h < 2; h++) {
                int r = wm * 32 + mt * 16 + h * 8 + q;
#pragma unroll
                for (int k = 0; k < 4; k++) lg[r * 4 + k] = acc[mt][h][k];
            }
    }
    __syncthreads();
    if (wn == 1 && (lane & 3) == 0) {
#pragma unroll
        for (int mt = 0; mt < 2; mt++)
#pragma unroll
            for (int h = 0; h < 2; h++) {
                int r = wm * 32 + mt * 16 + h * 8 + q;
#pragma unroll
                for (int k = 0; k < 4; k++) lg[r * 4 + k] += acc[mt][h][k];
            }
    }
    __syncthreads();

    // ---- per-row log-softmax + gather + mask, block reduce, one atomicAdd ----
    float contrib = 0.f;
    if (tid < 128) {
        int t = m0 + tid;
        if (t < len) {
            float l0 = lg[tid * 4 + 0] + __ldg(b2 + 0);
            float l1 = lg[tid * 4 + 1] + __ldg(b2 + 1);
            float l2 = lg[tid * 4 + 2] + __ldg(b2 + 2);
            float l3 = lg[tid * 4 + 3] + __ldg(b2 + 3);
            float mx = fmaxf(fmaxf(l0, l1), fmaxf(l2, l3));
            float e = expf(l0 - mx) + expf(l1 - mx) + expf(l2 - mx) + expf(l3 - mx);
            float lse = mx + logf(e);
            int a = __ldg(actions + (size_t)b * MAXT + t);
            float la = (a == 0) ? l0 : (a == 1) ? l1 : (a == 2) ? l2 : l3;
            contrib = la - lse;
        }
    }
#pragma unroll
    for (int o = 16; o; o >>= 1) contrib += __shfl_xor_sync(0xffffffffu, contrib, o);
    __syncthreads();
    if (lane == 0) lg[512 + wid] = contrib;
    __syncthreads();
    if (tid == 0) {
        float tot = 0.f;
#pragma unroll
        for (int w = 0; w < 8; w++) tot += lg[512 + w];
        atomicAdd(out, -tot);
    }
}

// ---------------- launcher ----------------
extern "C" void kernel_launch(void* const* d_in, const int* in_sizes, int n_in,
                              void* d_out, int out_size) {
    const float* s_i     = (const float*)d_in[0];
    const int*   actions = (const int*)d_in[1];
    const int*   lengths = (const int*)d_in[2];
    const float* W1      = (const float*)d_in[3];
    const float* b1      = (const float*)d_in[4];
    const float* W2      = (const float*)d_in[5];
    const float* b2      = (const float*)d_in[6];
    float* out = (float*)d_out;

    static bool attr_set = false;
    if (!attr_set) {
        cudaFuncSetAttribute(traj_main_kernel,
                             cudaFuncAttributeMaxDynamicSharedMemorySize, SMEM_BYTES);
        attr_set = true;
    }

    conv_s_kernel<<<NB_B * TP1, 128>>>(s_i, lengths, out);
    conv_w1t_kernel<<<dim3(H_DIM / 32, S_DIM / 32), dim3(32, 8)>>>(W1);
    traj_main_kernel<<<dim3(TP1 / BM, NB_B), 256, SMEM_BYTES>>>(actions, lengths, b1, W2, b2, out);
}

// round 5
// speedup vs baseline: 1.8277x; 1.8277x over previous
#include <cuda_runtime.h>
#include <cuda_bf16.h>
#include <cstdint>
#include <cstddef>

// ---------------- problem constants ----------------
#define NB_B   64
#define MAXT   511
#define TP1    512
#define S_DIM  1024
#define H_DIM  4096

// ---------------- tiling ----------------
#define BM 128
#define BN 256            // H columns per chunk
#define BK 64             // K per pipeline stage
#define N_CHUNKS  (H_DIM / BN)     // 16
#define K_STAGES  (S_DIM / BK)     // 16
#define TOT_GS    (N_CHUNKS * K_STAGES)  // 256
#define MAX_TILES 256     // worst case ceil(64*510/128) = 255

#define ROW_B  144        // 64 bf16 = 128B data + 16B pad (conflict-free ldmatrix)

// ---------------- SMEM layout: 3 pipeline stages + scratch ----------------
#define A_BYTES   (BM * ROW_B)          // 18432
#define B_BYTES   (BN * ROW_B)          // 36864
#define STG_BYTES (A_BYTES + B_BYTES)   // 55296
#define SM_LG     (3 * STG_BYTES)       // 165888
#define SMEM_BYTES (SM_LG + 4096)       // 169984

// ---------------- scratch (device globals; BSS zero-initialized) ----------
__device__ __align__(1024) __nv_bfloat16 g_s[(size_t)NB_B * TP1 * S_DIM];   // COMPACTED live rows (bf16); tail rows stay 0
__device__ __align__(1024) __nv_bfloat16 g_w1t[(size_t)H_DIM * S_DIM];      // W1^T bf16 (N-major rows, K contig)
__device__ int g_act[(size_t)NB_B * MAXT];   // per compacted row: action id
__device__ int g_off[NB_B + 1];              // row offsets per batch
__device__ int g_nrows;                      // total live rows

// ---------------- PTX helpers (all baseline <= sm_90 features) ----------------
__device__ __forceinline__ uint32_t smem_u32(const void* p) {
    uint32_t a;
    asm("{ .reg .u64 t; cvta.to.shared.u64 t, %1; cvt.u32.u64 %0, t; }" : "=r"(a) : "l"(p));
    return a;
}

__device__ __forceinline__ void cp_async16(uint32_t dst, const void* src) {
    asm volatile("cp.async.cg.shared.global [%0], [%1], 16;" :: "r"(dst), "l"(src) : "memory");
}
#define CP_COMMIT()  asm volatile("cp.async.commit_group;" ::: "memory")
#define CP_WAIT1()   asm volatile("cp.async.wait_group 1;" ::: "memory")

__device__ __forceinline__ void ldsm4(uint32_t* r, uint32_t addr) {
    asm volatile("ldmatrix.sync.aligned.m8n8.x4.shared.b16 {%0,%1,%2,%3}, [%4];"
                 : "=r"(r[0]), "=r"(r[1]), "=r"(r[2]), "=r"(r[3]) : "r"(addr));
}

__device__ __forceinline__ void mma16816(float* d, const uint32_t* a, const uint32_t* b) {
    asm volatile(
        "mma.sync.aligned.m16n8k16.row.col.f32.bf16.bf16.f32 "
        "{%0,%1,%2,%3}, {%4,%5,%6,%7}, {%8,%9}, {%0,%1,%2,%3};"
        : "+f"(d[0]), "+f"(d[1]), "+f"(d[2]), "+f"(d[3])
        : "r"(a[0]), "r"(a[1]), "r"(a[2]), "r"(a[3]), "r"(b[0]), "r"(b[1]));
}

// ---------------- kernel 0: prefix sum of lengths (+ un-poison out) ----------
__global__ void prefix_kernel(const int* __restrict__ lengths, float* __restrict__ out) {
    if (threadIdx.x == 0) {
        out[0] = 0.0f;
        int acc = 0;
        for (int b = 0; b < NB_B; b++) {
            g_off[b] = acc;
            int l = lengths[b];
            if (l > MAXT) l = MAXT;
            if (l < 0) l = 0;
            acc += l;
        }
        g_off[NB_B] = acc;
        g_nrows = acc;
    }
}

// ---------------- kernel 1: compacting fp32->bf16 conversion of live rows ----
__global__ void conv_s_kernel(const float* __restrict__ s,
                              const int* __restrict__ lengths,
                              const int* __restrict__ actions) {
    int t = blockIdx.x;               // 0..MAXT-1
    int b = blockIdx.y;
    int len = lengths[b];
    if (len > MAXT) len = MAXT;
    if (t >= len) return;

    int dstRow = g_off[b] + t;
    const float4* src = (const float4*)(s + ((size_t)b * TP1 + t) * S_DIM);
    __nv_bfloat162* dst = (__nv_bfloat162*)(g_s + (size_t)dstRow * S_DIM);
    for (int i = threadIdx.x; i < S_DIM / 4; i += blockDim.x) {
        float4 v = src[i];
        dst[i * 2 + 0] = __floats2bfloat162_rn(v.x, v.y);
        dst[i * 2 + 1] = __floats2bfloat162_rn(v.z, v.w);
    }
    if (threadIdx.x == 0)
        g_act[dstRow] = actions[(size_t)b * MAXT + t];
}

// ---------------- kernel 2: W1 (S,H) fp32 -> W1^T (H,S) bf16 ----------------
__global__ void conv_w1t_kernel(const float* __restrict__ W1) {
    __shared__ float tile[32][33];
    int n0 = blockIdx.x * 32;
    int k0 = blockIdx.y * 32;
    for (int r = threadIdx.y; r < 32; r += 8)
        tile[r][threadIdx.x] = W1[(size_t)(k0 + r) * H_DIM + n0 + threadIdx.x];
    __syncthreads();
    for (int r = threadIdx.y; r < 32; r += 8)
        g_w1t[(size_t)(n0 + r) * S_DIM + k0 + threadIdx.x] =
            __float2bfloat16(tile[threadIdx.x][r]);
}

// ---------------- main fused kernel ----------------
__global__ void __launch_bounds__(256, 1)
traj_main_kernel(const float* __restrict__ b1,
                 const float* __restrict__ W2,
                 const float* __restrict__ b2,
                 float* __restrict__ out) {
    int nrows = g_nrows;
    int m0 = blockIdx.x * BM;
    if (m0 >= nrows) return;          // tile beyond live rows

    extern __shared__ char smem[];
    uint32_t sb = smem_u32(smem);
    float* lg = (float*)(smem + SM_LG);

    int tid = threadIdx.x;
    int wid = tid >> 5;
    int lane = tid & 31;
    int wm = wid & 3;                 // M strip (32 rows)
    int wn = wid >> 2;                // N half (128 cols)

    const __nv_bfloat16* Abase = g_s + (size_t)m0 * S_DIM;

    // per-lane ldmatrix address components
    int aRow = wm * 32 + (lane & 15);              // + mt*16
    int aKof = (lane >> 4) * 8;                    // elements
    int bRow = wn * 128 + ((lane & 16) ? 8 : 0) + (lane & 7);   // + p*16
    int bKof = ((lane >> 3) & 1) * 8;

    auto issue = [&](int gs) {
        int nc = gs >> 4, s = gs & 15;
        int k0 = s * BK;
        const __nv_bfloat16* ag = Abase + k0;
        const __nv_bfloat16* bg = g_w1t + (size_t)(nc * BN) * S_DIM + k0;
        uint32_t stg = sb + (uint32_t)((gs % 3) * STG_BYTES);
        uint32_t Ab = stg;
        uint32_t Bb = stg + A_BYTES;
#pragma unroll
        for (int t = 0; t < 4; t++) {              // A: 128 rows x 8 chunks
            int idx = tid + t * 256;
            int row = idx >> 3, ch = idx & 7;
            cp_async16(Ab + row * ROW_B + ch * 16, ag + (size_t)row * S_DIM + ch * 8);
        }
#pragma unroll
        for (int t = 0; t < 8; t++) {              // B: 256 rows x 8 chunks
            int idx = tid + t * 256;
            int row = idx >> 3, ch = idx & 7;
            cp_async16(Bb + row * ROW_B + ch * 16, bg + (size_t)row * S_DIM + ch * 8);
        }
        CP_COMMIT();
    };

    float c[2][16][4];
#pragma unroll
    for (int mt = 0; mt < 2; mt++)
#pragma unroll
        for (int nt = 0; nt < 16; nt++)
#pragma unroll
            for (int k = 0; k < 4; k++) c[mt][nt][k] = 0.f;

    float acc[2][2][4] = {};          // [mt][rowhalf][logit]

    issue(0);
    issue(1);

#pragma unroll 1
    for (int gs = 0; gs < TOT_GS; gs++) {
        CP_WAIT1();                   // stage gs group complete (this thread)
        __syncthreads();              // cross-thread visibility + buffer-reuse fence

        // refill buffer (gs+2)%3: its last readers were stage gs-1, which all
        // warps finished before this barrier.
        if (gs + 2 < TOT_GS) issue(gs + 2);
        else                 CP_COMMIT();          // keep group cadence

        uint32_t stg = sb + (uint32_t)((gs % 3) * STG_BYTES);
        uint32_t Ab = stg;
        uint32_t Bb = stg + A_BYTES;
#pragma unroll
        for (int kk = 0; kk < 4; kk++) {           // 4 x k16 per stage
            uint32_t a0[4], a1[4];
            ldsm4(a0, Ab + (uint32_t)(aRow * ROW_B)        + (uint32_t)(kk * 16 + aKof) * 2);
            ldsm4(a1, Ab + (uint32_t)((aRow + 16) * ROW_B) + (uint32_t)(kk * 16 + aKof) * 2);
#pragma unroll
            for (int p = 0; p < 8; p++) {          // n-tile pairs
                uint32_t bf[4];
                ldsm4(bf, Bb + (uint32_t)((bRow + p * 16) * ROW_B) + (uint32_t)(kk * 16 + bKof) * 2);
                mma16816(c[0][2 * p],     a0, bf);
                mma16816(c[0][2 * p + 1], a0, bf + 2);
                mma16816(c[1][2 * p],     a1, bf);
                mma16816(c[1][2 * p + 1], a1, bf + 2);
            }
        }

        if ((gs & 15) == 15) {
            // ---- fused epilogue for N-chunk (gs>>4): relu + 4-wide W2 dot ----
            int nbch = (gs >> 4) * BN + wn * 128;
#pragma unroll
            for (int mt = 0; mt < 2; mt++)
#pragma unroll
                for (int nt = 0; nt < 16; nt++) {
                    int n0 = nbch + nt * 8 + (lane & 3) * 2;
#pragma unroll
                    for (int j = 0; j < 2; j++) {
                        int n = n0 + j;
                        float bb = __ldg(b1 + n);
                        float4 w = __ldg((const float4*)(W2 + (size_t)n * 32));
                        float h0 = fmaxf(c[mt][nt][j] + bb, 0.f);
                        float h1 = fmaxf(c[mt][nt][2 + j] + bb, 0.f);
                        acc[mt][0][0] += h0 * w.x; acc[mt][0][1] += h0 * w.y;
                        acc[mt][0][2] += h0 * w.z; acc[mt][0][3] += h0 * w.w;
                        acc[mt][1][0] += h1 * w.x; acc[mt][1][1] += h1 * w.y;
                        acc[mt][1][2] += h1 * w.z; acc[mt][1][3] += h1 * w.w;
                        c[mt][nt][j] = 0.f; c[mt][nt][2 + j] = 0.f;   // reset for next chunk
                    }
                }
        }
    }

    // ---- reduce 4-logit partials: quad shuffle, then combine the 2 N-halves ----
#pragma unroll
    for (int mt = 0; mt < 2; mt++)
#pragma unroll
        for (int h = 0; h < 2; h++)
#pragma unroll
            for (int k = 0; k < 4; k++) {
                float v = acc[mt][h][k];
                v += __shfl_xor_sync(0xffffffffu, v, 1);
                v += __shfl_xor_sync(0xffffffffu, v, 2);
                acc[mt][h][k] = v;
            }
    int q = lane >> 2;
    if (wn == 0 && (lane & 3) == 0) {
#pragma unroll
        for (int mt = 0; mt < 2; mt++)
#pragma unroll
            for (int h = 0; h < 2; h++) {
                int r = wm * 32 + mt * 16 + h * 8 + q;
#pragma unroll
                for (int k = 0; k < 4; k++) lg[r * 4 + k] = acc[mt][h][k];
            }
    }
    __syncthreads();
    if (wn == 1 && (lane & 3) == 0) {
#pragma unroll
        for (int mt = 0; mt < 2; mt++)
#pragma unroll
            for (int h = 0; h < 2; h++) {
                int r = wm * 32 + mt * 16 + h * 8 + q;
#pragma unroll
                for (int k = 0; k < 4; k++) lg[r * 4 + k] += acc[mt][h][k];
            }
    }
    __syncthreads();

    // ---- per-row log-softmax + gather (mask is implicit: rows are compacted) ----
    float contrib = 0.f;
    if (tid < 128) {
        int r = m0 + tid;
        if (r < nrows) {
            float l0 = lg[tid * 4 + 0] + __ldg(b2 + 0);
            float l1 = lg[tid * 4 + 1] + __ldg(b2 + 1);
            float l2 = lg[tid * 4 + 2] + __ldg(b2 + 2);
            float l3 = lg[tid * 4 + 3] + __ldg(b2 + 3);
            float mx = fmaxf(fmaxf(l0, l1), fmaxf(l2, l3));
            float e = expf(l0 - mx) + expf(l1 - mx) + expf(l2 - mx) + expf(l3 - mx);
            float lse = mx + logf(e);
            int a = g_act[r];
            float la = (a == 0) ? l0 : (a == 1) ? l1 : (a == 2) ? l2 : l3;
            contrib = la - lse;
        }
    }
#pragma unroll
    for (int o = 16; o; o >>= 1) contrib += __shfl_xor_sync(0xffffffffu, contrib, o);
    __syncthreads();
    if (lane == 0) lg[512 + wid] = contrib;
    __syncthreads();
    if (tid == 0) {
        float tot = 0.f;
#pragma unroll
        for (int w = 0; w < 8; w++) tot += lg[512 + w];
        atomicAdd(out, -tot);
    }
}

// ---------------- launcher ----------------
extern "C" void kernel_launch(void* const* d_in, const int* in_sizes, int n_in,
                              void* d_out, int out_size) {
    const float* s_i     = (const float*)d_in[0];
    const int*   actions = (const int*)d_in[1];
    const int*   lengths = (const int*)d_in[2];
    const float* W1      = (const float*)d_in[3];
    const float* b1      = (const float*)d_in[4];
    const float* W2      = (const float*)d_in[5];
    const float* b2      = (const float*)d_in[6];
    float* out = (float*)d_out;

    static bool attr_set = false;
    if (!attr_set) {
        cudaFuncSetAttribute(traj_main_kernel,
                             cudaFuncAttributeMaxDynamicSharedMemorySize, SMEM_BYTES);
        attr_set = true;
    }

    prefix_kernel<<<1, 32>>>(lengths, out);
    conv_s_kernel<<<dim3(MAXT, NB_B), 128>>>(s_i, lengths, actions);
    conv_w1t_kernel<<<dim3(H_DIM / 32, S_DIM / 32), dim3(32, 8)>>>(W1);
    traj_main_kernel<<<MAX_TILES, 256, SMEM_BYTES>>>(b1, W2, b2, out);
}

// round 6
// speedup vs baseline: 1.8404x; 1.0070x over previous
#include <cuda_runtime.h>
#include <cuda_bf16.h>
#include <cstdint>
#include <cstddef>

// ---------------- problem constants ----------------
#define NB_B   64
#define MAXT   511
#define TP1    512
#define S_DIM  1024
#define H_DIM  4096

// ---------------- tiling ----------------
#define BM 128
#define BN 256            // H columns per chunk
#define BK 64             // K per pipeline stage
#define N_CHUNKS  (H_DIM / BN)     // 16
#define K_STAGES  (S_DIM / BK)     // 16
#define TOT_GS    (N_CHUNKS * K_STAGES)  // 256
#define MAX_TILES 256     // worst case ceil(64*510/128) = 255
#define NTHREADS  512     // 16 warps: 4(M) x 4(N)

#define ROW_B  144        // 64 bf16 = 128B data + 16B pad (conflict-free ldmatrix)

// ---------------- SMEM layout: 3 pipeline stages + scratch ----------------
#define A_BYTES   (BM * ROW_B)          // 18432
#define B_BYTES   (BN * ROW_B)          // 36864
#define STG_BYTES (A_BYTES + B_BYTES)   // 55296
#define SM_LG     (3 * STG_BYTES)       // 165888
#define SMEM_BYTES (SM_LG + 4096)       // 169984

// ---------------- scratch (device globals; BSS zero-initialized) ----------
__device__ __align__(1024) __nv_bfloat16 g_s[(size_t)NB_B * TP1 * S_DIM];   // COMPACTED live rows; tail stays 0
__device__ __align__(1024) __nv_bfloat16 g_w1t[(size_t)H_DIM * S_DIM];      // W1^T bf16 (N-major rows, K contig)
__device__ int g_act[(size_t)NB_B * MAXT];   // per compacted row: action id
__device__ int g_off[NB_B + 1];              // row offsets per batch
__device__ int g_nrows;                      // total live rows

// ---------------- PTX helpers ----------------
__device__ __forceinline__ uint32_t smem_u32(const void* p) {
    uint32_t a;
    asm("{ .reg .u64 t; cvta.to.shared.u64 t, %1; cvt.u32.u64 %0, t; }" : "=r"(a) : "l"(p));
    return a;
}

__device__ __forceinline__ void cp_async16(uint32_t dst, const void* src) {
    asm volatile("cp.async.cg.shared.global [%0], [%1], 16;" :: "r"(dst), "l"(src) : "memory");
}
#define CP_COMMIT()  asm volatile("cp.async.commit_group;" ::: "memory")
#define CP_WAIT1()   asm volatile("cp.async.wait_group 1;" ::: "memory")

__device__ __forceinline__ void ldsm4(uint32_t* r, uint32_t addr) {
    asm volatile("ldmatrix.sync.aligned.m8n8.x4.shared.b16 {%0,%1,%2,%3}, [%4];"
                 : "=r"(r[0]), "=r"(r[1]), "=r"(r[2]), "=r"(r[3]) : "r"(addr));
}

__device__ __forceinline__ void mma16816(float* d, const uint32_t* a, const uint32_t* b) {
    asm volatile(
        "mma.sync.aligned.m16n8k16.row.col.f32.bf16.bf16.f32 "
        "{%0,%1,%2,%3}, {%4,%5,%6,%7}, {%8,%9}, {%0,%1,%2,%3};"
        : "+f"(d[0]), "+f"(d[1]), "+f"(d[2]), "+f"(d[3])
        : "r"(a[0]), "r"(a[1]), "r"(a[2]), "r"(a[3]), "r"(b[0]), "r"(b[1]));
}

// ---------------- kernel 0: prefix sum of lengths (+ un-poison out) ----------
__global__ void prefix_kernel(const int* __restrict__ lengths, float* __restrict__ out) {
    if (threadIdx.x == 0) {
        out[0] = 0.0f;
        int acc = 0;
        for (int b = 0; b < NB_B; b++) {
            g_off[b] = acc;
            int l = lengths[b];
            if (l > MAXT) l = MAXT;
            if (l < 0) l = 0;
            acc += l;
        }
        g_off[NB_B] = acc;
        g_nrows = acc;
    }
}

// ---------------- kernel 1: compacting fp32->bf16 conversion of live rows ----
__global__ void conv_s_kernel(const float* __restrict__ s,
                              const int* __restrict__ lengths,
                              const int* __restrict__ actions) {
    int t = blockIdx.x;               // 0..MAXT-1
    int b = blockIdx.y;
    int len = lengths[b];
    if (len > MAXT) len = MAXT;
    if (t >= len) return;

    int dstRow = g_off[b] + t;
    const float4* src = (const float4*)(s + ((size_t)b * TP1 + t) * S_DIM);
    __nv_bfloat162* dst = (__nv_bfloat162*)(g_s + (size_t)dstRow * S_DIM);
    for (int i = threadIdx.x; i < S_DIM / 4; i += blockDim.x) {
        float4 v = src[i];
        dst[i * 2 + 0] = __floats2bfloat162_rn(v.x, v.y);
        dst[i * 2 + 1] = __floats2bfloat162_rn(v.z, v.w);
    }
    if (threadIdx.x == 0)
        g_act[dstRow] = actions[(size_t)b * MAXT + t];
}

// ---------------- kernel 2: W1 (S,H) fp32 -> W1^T (H,S) bf16 ----------------
__global__ void conv_w1t_kernel(const float* __restrict__ W1) {
    __shared__ float tile[32][33];
    int n0 = blockIdx.x * 32;
    int k0 = blockIdx.y * 32;
    for (int r = threadIdx.y; r < 32; r += 8)
        tile[r][threadIdx.x] = W1[(size_t)(k0 + r) * H_DIM + n0 + threadIdx.x];
    __syncthreads();
    for (int r = threadIdx.y; r < 32; r += 8)
        g_w1t[(size_t)(n0 + r) * S_DIM + k0 + threadIdx.x] =
            __float2bfloat16(tile[threadIdx.x][r]);
}

// ---------------- main fused kernel (512 threads, 16 warps: 4M x 4N) --------
__global__ void __launch_bounds__(NTHREADS, 1)
traj_main_kernel(const float* __restrict__ b1,
                 const float* __restrict__ W2,
                 const float* __restrict__ b2,
                 float* __restrict__ out) {
    int nrows = g_nrows;
    int m0 = blockIdx.x * BM;
    if (m0 >= nrows) return;          // tile beyond live rows

    extern __shared__ char smem[];
    uint32_t sb = smem_u32(smem);
    float* lg = (float*)(smem + SM_LG);

    int tid = threadIdx.x;
    int wid = tid >> 5;
    int lane = tid & 31;
    int wm = wid & 3;                 // M strip (32 rows)
    int wn = wid >> 2;                // N quarter (64 cols)

    const __nv_bfloat16* Abase = g_s + (size_t)m0 * S_DIM;

    // per-lane ldmatrix address components
    int aRow = wm * 32 + (lane & 15);                           // + mt*16
    int aKof = (lane >> 4) * 8;                                 // elements
    int bRow = wn * 64 + ((lane & 16) ? 8 : 0) + (lane & 7);    // + p*16
    int bKof = ((lane >> 3) & 1) * 8;

    auto issue = [&](int gs) {
        int nc = gs >> 4, s = gs & 15;
        int k0 = s * BK;
        const __nv_bfloat16* ag = Abase + k0;
        const __nv_bfloat16* bg = g_w1t + (size_t)(nc * BN) * S_DIM + k0;
        uint32_t stg = sb + (uint32_t)((gs % 3) * STG_BYTES);
        uint32_t Ab = stg;
        uint32_t Bb = stg + A_BYTES;
#pragma unroll
        for (int t = 0; t < 2; t++) {              // A: 128 rows x 8 chunks = 1024
            int idx = tid + t * NTHREADS;
            int row = idx >> 3, ch = idx & 7;
            cp_async16(Ab + row * ROW_B + ch * 16, ag + (size_t)row * S_DIM + ch * 8);
        }
#pragma unroll
        for (int t = 0; t < 4; t++) {              // B: 256 rows x 8 chunks = 2048
            int idx = tid + t * NTHREADS;
            int row = idx >> 3, ch = idx & 7;
            cp_async16(Bb + row * ROW_B + ch * 16, bg + (size_t)row * S_DIM + ch * 8);
        }
        CP_COMMIT();
    };

    float c[2][8][4];                 // [mt][nt][frag] : 32x64 warp tile
#pragma unroll
    for (int mt = 0; mt < 2; mt++)
#pragma unroll
        for (int nt = 0; nt < 8; nt++)
#pragma unroll
            for (int k = 0; k < 4; k++) c[mt][nt][k] = 0.f;

    float acc[2][2][4] = {};          // [mt][rowhalf][logit]

    issue(0);
    issue(1);

#pragma unroll 1
    for (int gs = 0; gs < TOT_GS; gs++) {
        CP_WAIT1();                   // stage gs group complete (this thread)
        __syncthreads();              // cross-thread visibility + buffer-reuse fence

        // refill buffer (gs+2)%3: last readers were stage gs-1, pre-barrier.
        if (gs + 2 < TOT_GS) issue(gs + 2);
        else                 CP_COMMIT();          // keep group cadence

        uint32_t stg = sb + (uint32_t)((gs % 3) * STG_BYTES);
        uint32_t Ab = stg;
        uint32_t Bb = stg + A_BYTES;
#pragma unroll
        for (int kk = 0; kk < 4; kk++) {           // 4 x k16 per stage
            uint32_t a0[4], a1[4];
            ldsm4(a0, Ab + (uint32_t)(aRow * ROW_B)        + (uint32_t)(kk * 16 + aKof) * 2);
            ldsm4(a1, Ab + (uint32_t)((aRow + 16) * ROW_B) + (uint32_t)(kk * 16 + aKof) * 2);
#pragma unroll
            for (int p = 0; p < 4; p++) {          // n-tile pairs (16 cols each)
                uint32_t bf[4];
                ldsm4(bf, Bb + (uint32_t)((bRow + p * 16) * ROW_B) + (uint32_t)(kk * 16 + bKof) * 2);
                mma16816(c[0][2 * p],     a0, bf);
                mma16816(c[0][2 * p + 1], a0, bf + 2);
                mma16816(c[1][2 * p],     a1, bf);
                mma16816(c[1][2 * p + 1], a1, bf + 2);
            }
        }

        if ((gs & 15) == 15) {
            // ---- fused epilogue for N-chunk (gs>>4): relu + 4-wide W2 dot ----
            int nbch = (gs >> 4) * BN + wn * 64;
#pragma unroll
            for (int mt = 0; mt < 2; mt++)
#pragma unroll
                for (int nt = 0; nt < 8; nt++) {
                    int n0 = nbch + nt * 8 + (lane & 3) * 2;
#pragma unroll
                    for (int j = 0; j < 2; j++) {
                        int n = n0 + j;
                        float bb = __ldg(b1 + n);
                        float4 w = __ldg((const float4*)(W2 + (size_t)n * 32));
                        float h0 = fmaxf(c[mt][nt][j] + bb, 0.f);
                        float h1 = fmaxf(c[mt][nt][2 + j] + bb, 0.f);
                        acc[mt][0][0] += h0 * w.x; acc[mt][0][1] += h0 * w.y;
                        acc[mt][0][2] += h0 * w.z; acc[mt][0][3] += h0 * w.w;
                        acc[mt][1][0] += h1 * w.x; acc[mt][1][1] += h1 * w.y;
                        acc[mt][1][2] += h1 * w.z; acc[mt][1][3] += h1 * w.w;
                        c[mt][nt][j] = 0.f; c[mt][nt][2 + j] = 0.f;   // reset for next chunk
                    }
                }
        }
    }

    // ---- reduce logit partials: quad shuffle, then combine 4 N-warps in smem ----
#pragma unroll
    for (int mt = 0; mt < 2; mt++)
#pragma unroll
        for (int h = 0; h < 2; h++)
#pragma unroll
            for (int k = 0; k < 4; k++) {
                float v = acc[mt][h][k];
                v += __shfl_xor_sync(0xffffffffu, v, 1);
                v += __shfl_xor_sync(0xffffffffu, v, 2);
                acc[mt][h][k] = v;
            }

    lg[tid] = 0.f;                    // zero 512 floats (128 rows x 4 logits)
    __syncthreads();

    int q = lane >> 2;
    if ((lane & 3) == 0) {
#pragma unroll
        for (int mt = 0; mt < 2; mt++)
#pragma unroll
            for (int h = 0; h < 2; h++) {
                int r = wm * 32 + mt * 16 + h * 8 + q;
#pragma unroll
                for (int k = 0; k < 4; k++)
                    atomicAdd(&lg[r * 4 + k], acc[mt][h][k]);
            }
    }
    __syncthreads();

    // ---- per-row log-softmax + gather (mask implicit: rows compacted) ----
    float contrib = 0.f;
    if (tid < 128) {
        int r = m0 + tid;
        if (r < nrows) {
            float l0 = lg[tid * 4 + 0] + __ldg(b2 + 0);
            float l1 = lg[tid * 4 + 1] + __ldg(b2 + 1);
            float l2 = lg[tid * 4 + 2] + __ldg(b2 + 2);
            float l3 = lg[tid * 4 + 3] + __ldg(b2 + 3);
            float mx = fmaxf(fmaxf(l0, l1), fmaxf(l2, l3));
            float e = expf(l0 - mx) + expf(l1 - mx) + expf(l2 - mx) + expf(l3 - mx);
            float lse = mx + logf(e);
            int a = g_act[r];
            float la = (a == 0) ? l0 : (a == 1) ? l1 : (a == 2) ? l2 : l3;
            contrib = la - lse;
        }
    }
#pragma unroll
    for (int o = 16; o; o >>= 1) contrib += __shfl_xor_sync(0xffffffffu, contrib, o);
    __syncthreads();
    if (lane == 0) lg[512 + wid] = contrib;
    __syncthreads();
    if (tid == 0) {
        float tot = 0.f;
#pragma unroll
        for (int w = 0; w < 16; w++) tot += lg[512 + w];
        atomicAdd(out, -tot);
    }
}

// ---------------- launcher ----------------
extern "C" void kernel_launch(void* const* d_in, const int* in_sizes, int n_in,
                              void* d_out, int out_size) {
    const float* s_i     = (const float*)d_in[0];
    const int*   actions = (const int*)d_in[1];
    const int*   lengths = (const int*)d_in[2];
    const float* W1      = (const float*)d_in[3];
    const float* b1      = (const float*)d_in[4];
    const float* W2      = (const float*)d_in[5];
    const float* b2      = (const float*)d_in[6];
    float* out = (float*)d_out;

    static bool attr_set = false;
    if (!attr_set) {
        cudaFuncSetAttribute(traj_main_kernel,
                             cudaFuncAttributeMaxDynamicSharedMemorySize, SMEM_BYTES);
        attr_set = true;
    }

    prefix_kernel<<<1, 32>>>(lengths, out);
    conv_s_kernel<<<dim3(MAXT, NB_B), 128>>>(s_i, lengths, actions);
    conv_w1t_kernel<<<dim3(H_DIM / 32, S_DIM / 32), dim3(32, 8)>>>(W1);
    traj_main_kernel<<<MAX_TILES, NTHREADS, SMEM_BYTES>>>(b1, W2, b2, out);
}

// round 8
// speedup vs baseline: 1.9688x; 1.0698x over previous
#include <cuda_runtime.h>
#include <cuda_bf16.h>
#include <cstdint>
#include <cstddef>

// ---------------- problem constants ----------------
#define NB_B   64
#define MAXT   511
#define TP1    512
#define S_DIM  1024
#define H_DIM  4096

// ---------------- tiling ----------------
#define BM 128
#define BN 256            // H columns per chunk
#define BK 64             // K per pipeline stage
#define N_CHUNKS  (H_DIM / BN)     // 16
#define K_STAGES  (S_DIM / BK)     // 16
#define TOT_GS    (N_CHUNKS * K_STAGES)  // 256
#define MAX_TILES 256     // worst case ceil(64*510/128) = 255
#define NTHREADS  256     // 8 warps: 2(M) x 4(N), warp tile 64x64

#define ROW_B  144        // 64 bf16 = 128B data + 16B pad (conflict-free ldmatrix)

// ---------------- SMEM layout: 3 pipeline stages + scratch ----------------
#define A_BYTES   (BM * ROW_B)          // 18432
#define B_BYTES   (BN * ROW_B)          // 36864
#define STG_BYTES (A_BYTES + B_BYTES)   // 55296
#define SM_LG     (3 * STG_BYTES)       // 165888
#define SMEM_BYTES (SM_LG + 4096)       // 169984

// ---------------- scratch (device globals; BSS zero-initialized) ----------
__device__ __align__(1024) __nv_bfloat16 g_s[(size_t)NB_B * TP1 * S_DIM];   // COMPACTED live rows; tail stays 0
__device__ __align__(1024) __nv_bfloat16 g_w1t[(size_t)H_DIM * S_DIM];      // W1^T bf16 (N-major rows, K contig)
__device__ int g_act[(size_t)NB_B * MAXT];   // per compacted row: action id
__device__ int g_off[NB_B + 1];              // row offsets per batch
__device__ int g_nrows;                      // total live rows

// ---------------- PTX helpers ----------------
__device__ __forceinline__ uint32_t smem_u32(const void* p) {
    uint32_t a;
    asm("{ .reg .u64 t; cvta.to.shared.u64 t, %1; cvt.u32.u64 %0, t; }" : "=r"(a) : "l"(p));
    return a;
}

__device__ __forceinline__ void cp_async16(uint32_t dst, const void* src) {
    asm volatile("cp.async.cg.shared.global [%0], [%1], 16;" :: "r"(dst), "l"(src) : "memory");
}
#define CP_COMMIT()  asm volatile("cp.async.commit_group;" ::: "memory")
#define CP_WAIT1()   asm volatile("cp.async.wait_group 1;" ::: "memory")
#define CP_WAIT2()   asm volatile("cp.async.wait_group 2;" ::: "memory")

__device__ __forceinline__ void ldsm4(uint32_t* r, uint32_t addr) {
    asm volatile("ldmatrix.sync.aligned.m8n8.x4.shared.b16 {%0,%1,%2,%3}, [%4];"
                 : "=r"(r[0]), "=r"(r[1]), "=r"(r[2]), "=r"(r[3]) : "r"(addr));
}

__device__ __forceinline__ void mma16816(float* d, const uint32_t* a, const uint32_t* b) {
    asm volatile(
        "mma.sync.aligned.m16n8k16.row.col.f32.bf16.bf16.f32 "
        "{%0,%1,%2,%3}, {%4,%5,%6,%7}, {%8,%9}, {%0,%1,%2,%3};"
        : "+f"(d[0]), "+f"(d[1]), "+f"(d[2]), "+f"(d[3])
        : "r"(a[0]), "r"(a[1]), "r"(a[2]), "r"(a[3]), "r"(b[0]), "r"(b[1]));
}

// ---------------- kernel 0: prefix sum of lengths (+ un-poison out) ----------
__global__ void prefix_kernel(const int* __restrict__ lengths, float* __restrict__ out) {
    if (threadIdx.x == 0) {
        out[0] = 0.0f;
        int acc = 0;
        for (int b = 0; b < NB_B; b++) {
            g_off[b] = acc;
            int l = lengths[b];
            if (l > MAXT) l = MAXT;
            if (l < 0) l = 0;
            acc += l;
        }
        g_off[NB_B] = acc;
        g_nrows = acc;
    }
}

// ---------------- kernel 1: compacting fp32->bf16 conversion of live rows ----
__global__ void conv_s_kernel(const float* __restrict__ s,
                              const int* __restrict__ lengths,
                              const int* __restrict__ actions) {
    int t = blockIdx.x;               // 0..MAXT-1
    int b = blockIdx.y;
    int len = lengths[b];
    if (len > MAXT) len = MAXT;
    if (t >= len) return;

    int dstRow = g_off[b] + t;
    const float4* src = (const float4*)(s + ((size_t)b * TP1 + t) * S_DIM);
    __nv_bfloat162* dst = (__nv_bfloat162*)(g_s + (size_t)dstRow * S_DIM);
    for (int i = threadIdx.x; i < S_DIM / 4; i += blockDim.x) {
        float4 v = src[i];
        dst[i * 2 + 0] = __floats2bfloat162_rn(v.x, v.y);
        dst[i * 2 + 1] = __floats2bfloat162_rn(v.z, v.w);
    }
    if (threadIdx.x == 0)
        g_act[dstRow] = actions[(size_t)b * MAXT + t];
}

// ---------------- kernel 2: W1 (S,H) fp32 -> W1^T (H,S) bf16 ----------------
__global__ void conv_w1t_kernel(const float* __restrict__ W1) {
    __shared__ float tile[32][33];
    int n0 = blockIdx.x * 32;
    int k0 = blockIdx.y * 32;
    for (int r = threadIdx.y; r < 32; r += 8)
        tile[r][threadIdx.x] = W1[(size_t)(k0 + r) * H_DIM + n0 + threadIdx.x];
    __syncthreads();
    for (int r = threadIdx.y; r < 32; r += 8)
        g_w1t[(size_t)(n0 + r) * S_DIM + k0 + threadIdx.x] =
            __float2bfloat16(tile[threadIdx.x][r]);
}

// ---------------- main fused kernel (256 threads, 8 warps: 2M x 4N) ---------
__global__ void __launch_bounds__(NTHREADS, 1)
traj_main_kernel(const float* __restrict__ b1,
                 const float* __restrict__ W2,
                 const float* __restrict__ b2,
                 float* __restrict__ out) {
    int nrows = g_nrows;
    int m0 = blockIdx.x * BM;
    if (m0 >= nrows) return;          // tile beyond live rows

    extern __shared__ char smem[];
    uint32_t sb = smem_u32(smem);
    float* lg = (float*)(smem + SM_LG);

    int tid = threadIdx.x;
    int wid = tid >> 5;
    int lane = tid & 31;
    int wm = wid & 1;                 // M half (64 rows)
    int wn = wid >> 1;                // N quarter (64 cols)

    const __nv_bfloat16* Abase = g_s + (size_t)m0 * S_DIM;

    // per-lane ldmatrix base byte offsets (within a stage buffer)
    uint32_t aOff0 = (uint32_t)((wm * 64 + (lane & 15)) * ROW_B + ((lane >> 4) * 8) * 2);
    uint32_t bOff0 = (uint32_t)((wn * 64 + ((lane & 16) ? 8 : 0) + (lane & 7)) * ROW_B
                                + (((lane >> 3) & 1) * 8) * 2);

    auto issue = [&](int gs) {
        int nc = gs >> 4, s = gs & 15;
        int k0 = s * BK;
        const __nv_bfloat16* ag = Abase + k0;
        const __nv_bfloat16* bg = g_w1t + (size_t)(nc * BN) * S_DIM + k0;
        uint32_t stg = sb + (uint32_t)((gs % 3) * STG_BYTES);
        uint32_t Ab = stg;
        uint32_t Bb = stg + A_BYTES;
#pragma unroll
        for (int t = 0; t < 4; t++) {              // A: 128 rows x 8 chunks = 1024
            int idx = tid + t * NTHREADS;
            int row = idx >> 3, ch = idx & 7;
            cp_async16(Ab + row * ROW_B + ch * 16, ag + (size_t)row * S_DIM + ch * 8);
        }
#pragma unroll
        for (int t = 0; t < 8; t++) {              // B: 256 rows x 8 chunks = 2048
            int idx = tid + t * NTHREADS;
            int row = idx >> 3, ch = idx & 7;
            cp_async16(Bb + row * ROW_B + ch * 16, bg + (size_t)row * S_DIM + ch * 8);
        }
        CP_COMMIT();
    };

    float c[4][8][4];                 // 64x64 warp tile: [mt][nt][frag]
#pragma unroll
    for (int mt = 0; mt < 4; mt++)
#pragma unroll
        for (int nt = 0; nt < 8; nt++)
#pragma unroll
            for (int k = 0; k < 4; k++) c[mt][nt][k] = 0.f;

    uint32_t fa[2][16], fb[2][16];    // double-buffered fragments (one k16 step each)

    // load fragments for k-step kk of the stage at 'stg' into buffer 'buf'
    auto ldfr = [&](int buf, uint32_t stg, int kk) {
        uint32_t Ab = stg + aOff0 + (uint32_t)kk * 32;
        uint32_t Bb = stg + A_BYTES + bOff0 + (uint32_t)kk * 32;
        ldsm4(&fa[buf][0],  Ab);
        ldsm4(&fa[buf][4],  Ab + 16 * ROW_B);
        ldsm4(&fa[buf][8],  Ab + 32 * ROW_B);
        ldsm4(&fa[buf][12], Ab + 48 * ROW_B);
        ldsm4(&fb[buf][0],  Bb);
        ldsm4(&fb[buf][4],  Bb + 16 * ROW_B);
        ldsm4(&fb[buf][8],  Bb + 32 * ROW_B);
        ldsm4(&fb[buf][12], Bb + 48 * ROW_B);
    };
    // 32 MMAs on buffer 'buf'
    auto mmast = [&](int buf) {
#pragma unroll
        for (int mt = 0; mt < 4; mt++)
#pragma unroll
            for (int p = 0; p < 4; p++) {
                mma16816(c[mt][2 * p],     &fa[buf][mt * 4], &fb[buf][p * 4]);
                mma16816(c[mt][2 * p + 1], &fa[buf][mt * 4], &fb[buf][p * 4 + 2]);
            }
    };

    // per-chunk epilogue: relu + b1, 4-wide W2 dot, quad-reduce, smem atomicAdd
    auto epilog = [&](int chunk) {
        float macc[4][2][4];
#pragma unroll
        for (int mt = 0; mt < 4; mt++)
#pragma unroll
            for (int h = 0; h < 2; h++)
#pragma unroll
                for (int k = 0; k < 4; k++) macc[mt][h][k] = 0.f;
        int nbase = chunk * BN + wn * 64;
#pragma unroll
        for (int mt = 0; mt < 4; mt++)
#pragma unroll
            for (int nt = 0; nt < 8; nt++) {
                int n0 = nbase + nt * 8 + (lane & 3) * 2;
#pragma unroll
                for (int j = 0; j < 2; j++) {
                    int n = n0 + j;
                    float bb = __ldg(b1 + n);
                    float4 w = __ldg((const float4*)(W2 + (size_t)n * 32));
                    float h0 = fmaxf(c[mt][nt][j] + bb, 0.f);
                    float h1 = fmaxf(c[mt][nt][2 + j] + bb, 0.f);
                    macc[mt][0][0] += h0 * w.x; macc[mt][0][1] += h0 * w.y;
                    macc[mt][0][2] += h0 * w.z; macc[mt][0][3] += h0 * w.w;
                    macc[mt][1][0] += h1 * w.x; macc[mt][1][1] += h1 * w.y;
                    macc[mt][1][2] += h1 * w.z; macc[mt][1][3] += h1 * w.w;
                    c[mt][nt][j] = 0.f; c[mt][nt][2 + j] = 0.f;   // reset for next chunk
                }
            }
#pragma unroll
        for (int mt = 0; mt < 4; mt++)
#pragma unroll
            for (int h = 0; h < 2; h++)
#pragma unroll
                for (int k = 0; k < 4; k++) {
                    float v = macc[mt][h][k];
                    v += __shfl_xor_sync(0xffffffffu, v, 1);
                    v += __shfl_xor_sync(0xffffffffu, v, 2);
                    macc[mt][h][k] = v;
                }
        if ((lane & 3) == 0) {
            int q = lane >> 2;
#pragma unroll
            for (int mt = 0; mt < 4; mt++)
#pragma unroll
                for (int h = 0; h < 2; h++) {
                    int r = wm * 64 + mt * 16 + h * 8 + q;
#pragma unroll
                    for (int k = 0; k < 4; k++)
                        atomicAdd(&lg[r * 4 + k], macc[mt][h][k]);
                }
        }
    };

    // ---- prologue ----
    lg[tid] = 0.f; lg[tid + 256] = 0.f;    // zero 512-entry logit table
    issue(0); issue(1); issue(2);
    CP_WAIT2();                            // stage 0 resident (this thread)
    __syncthreads();                       // all threads' stage-0 writes visible; lg zeroed
    ldfr(0, sb, 0);                        // stage 0, kk 0 -> buffer 0

#pragma unroll 1
    for (int gs = 0; gs < TOT_GS; gs++) {
        uint32_t stg = sb + (uint32_t)((gs % 3) * STG_BYTES);
        // invariant: buffer 0 holds kk0 frags of stage gs
        ldfr(1, stg, 1); mmast(0);
        ldfr(0, stg, 2); mmast(1);
        ldfr(1, stg, 3); mmast(0);
        if (gs + 1 < TOT_GS) {
            CP_WAIT1();                    // stage gs+1 group complete (this thread)
            __syncthreads();               // hides behind ~96 queued MMAs
            uint32_t nstg = sb + (uint32_t)(((gs + 1) % 3) * STG_BYTES);
            ldfr(0, nstg, 0);              // next stage kk0 while kk1-3 MMAs drain
            if (gs + 3 < TOT_GS) issue(gs + 3);   // refill freed buffer (gs%3)
        }
        mmast(1);                          // kk3
        if ((gs & 15) == 15) epilog(gs >> 4);
    }
    __syncthreads();                       // all epilogue atomics done

    // ---- per-row log-softmax + gather (mask implicit: rows compacted) ----
    float contrib = 0.f;
    if (tid < 128) {
        int r = m0 + tid;
        if (r < nrows) {
            float l0 = lg[tid * 4 + 0] + __ldg(b2 + 0);
            float l1 = lg[tid * 4 + 1] + __ldg(b2 + 1);
            float l2 = lg[tid * 4 + 2] + __ldg(b2 + 2);
            float l3 = lg[tid * 4 + 3] + __ldg(b2 + 3);
            float mx = fmaxf(fmaxf(l0, l1), fmaxf(l2, l3));
            float e = expf(l0 - mx) + expf(l1 - mx) + expf(l2 - mx) + expf(l3 - mx);
            float lse = mx + logf(e);
            int a = g_act[r];
            float la = (a == 0) ? l0 : (a == 1) ? l1 : (a == 2) ? l2 : l3;
            contrib = la - lse;
        }
    }
#pragma unroll
    for (int o = 16; o; o >>= 1) contrib += __shfl_xor_sync(0xffffffffu, contrib, o);
    __syncthreads();
    if (lane == 0) lg[512 + wid] = contrib;
    __syncthreads();
    if (tid == 0) {
        float tot = 0.f;
#pragma unroll
        for (int w = 0; w < 8; w++) tot += lg[512 + w];
        atomicAdd(out, -tot);
    }
}

// ---------------- launcher ----------------
extern "C" void kernel_launch(void* const* d_in, const int* in_sizes, int n_in,
                              void* d_out, int out_size) {
    const float* s_i     = (const float*)d_in[0];
    const int*   actions = (const int*)d_in[1];
    const int*   lengths = (const int*)d_in[2];
    const float* W1      = (const float*)d_in[3];
    const float* b1      = (const float*)d_in[4];
    const float* W2      = (const float*)d_in[5];
    const float* b2      = (const float*)d_in[6];
    float* out = (float*)d_out;

    static bool attr_set = false;
    if (!attr_set) {
        cudaFuncSetAttribute(traj_main_kernel,
                             cudaFuncAttributeMaxDynamicSharedMemorySize, SMEM_BYTES);
        attr_set = true;
    }

    prefix_kernel<<<1, 32>>>(lengths, out);
    conv_s_kernel<<<dim3(MAXT, NB_B), 128>>>(s_i, lengths, actions);
    conv_w1t_kernel<<<dim3(H_DIM / 32, S_DIM / 32), dim3(32, 8)>>>(W1);
    traj_main_kernel<<<MAX_TILES, NTHREADS, SMEM_BYTES>>>(b1, W2, b2, out);
}